// round 16
// baseline (speedup 1.0000x reference)
#include <cuda_runtime.h>
#include <math.h>

typedef unsigned long long u64;

#define NB   65536
#define DD   44
#define HH   256
#define EE   4
#define AA   8
#define TILE 32
#define NT   256
#define NTILES (NB / TILE)

// dynamic smem layout (floats) — activation buffers TRANSPOSED: buf[feature][row]
#define OFF_A1    (TILE*DD)               // XsT: [0,1408)
#define OFF_A2    (OFF_A1 + HH*TILE)      // A1:  [1408,9600)  (XcT staged in A1[0:1408))
#define OFF_RED   (OFF_A2 + HH*TILE)      // A2:  [9600,17792); upper half doubles as LN scratch
#define OFF_MRS   (OFF_RED + 512)
#define OFF_LG    (OFF_MRS + 64)          // lg[128] -> int scratch in expert phase
#define OFF_GLIST (OFF_LG + TILE*EE)      // int glist[128]
#define OFF_GCOMB (OFF_GLIST + TILE*EE)   // float gcomb[128]
#define OFF_ECNT  (OFF_GCOMB + TILE*EE)
#define SMEM_FLOATS (OFF_ECNT + 8)
#define SMEM_BYTES  (SMEM_FLOATS * 4)

// Row swizzle inside A1/A2 (bank de-conflict): feature k's row r lives at
// slot r ^ swz(k). swz is a multiple of 4 XORed into row bits 2..4.
// Period 32 in k: unrolled loops fold swz to immediates.
__device__ __forceinline__ int swz(int k) { return 4 * ((k >> 2) & 7); }

// ---------- packed f32x2 helpers ----------
__device__ __forceinline__ u64 ffma2(u64 a, u64 b, u64 c) {
    u64 d;
    asm("fma.rn.f32x2 %0, %1, %2, %3;" : "=l"(d) : "l"(a), "l"(b), "l"(c));
    return d;
}
__device__ __forceinline__ u64 fadd2(u64 a, u64 b) {
    u64 d;
    asm("add.rn.f32x2 %0, %1, %2;" : "=l"(d) : "l"(a), "l"(b));
    return d;
}
__device__ __forceinline__ u64 dup2(float w) {
    u64 d; unsigned int ui = __float_as_uint(w);
    asm("mov.b64 %0, {%1, %1};" : "=l"(d) : "r"(ui));
    return d;
}
__device__ __forceinline__ float2 unpack2(u64 a) {
    float2 f;
    asm("mov.b64 {%0, %1}, %2;" : "=f"(f.x), "=f"(f.y) : "l"(a));
    return f;
}
__device__ __forceinline__ float softplus1(float x) {
    return fmaxf(x, 0.f) + log1pf(expf(-fabsf(x))) + 1.f;
}

// Prefetched first weight block (k = 0..3, 4 cols per thread) for gemm256_ln.
struct W44 { float4 a, b, c, d; };
__device__ __forceinline__ W44 pref4(const float* Wp_c0) {
    W44 w;
    w.a = __ldcg((const float4*)(Wp_c0 + 0 * HH));
    w.b = __ldcg((const float4*)(Wp_c0 + 1 * HH));
    w.c = __ldcg((const float4*)(Wp_c0 + 2 * HH));
    w.d = __ldcg((const float4*)(Wp_c0 + 3 * HH));
    return w;
}

// ---------- fused GEMM + LayerNorm + ReLU, row-sparse ----------
// Out^T[256][32] = relu(LN(In^T[K][32] @ W[K][256] + bias) * g + b)
// thread tile: 8 rows (4 packed pairs) x 4 cols. K % 4 == 0.
// Weights via __ldcg. wpre = PREFETCHED block k=0..3 (loaded by the caller
// BEFORE the barrier preceding this call, hiding L2 latency in the barrier).
// SWIN: input row-swizzled (A1/A2) or not (XsT). Output ALWAYS stored swizzled.
// NO TRAILING SYNC: caller must __syncthreads() before any thread reads Out.
// Internal syncs B and C only. In may alias Out (stores after sync-C; all In
// reads before sync-B). scratch must not alias In (pre-fenced by caller).
// Row-groups with r0 >= cnt skip the mainloop (cnt % 8 == 0 -> warp-uniform).
template<int K, bool SWIN, int UNR>
__device__ __forceinline__ void gemm256_ln(const float* In, const float* W,
                                           const float* bias,
                                           const float* g,
                                           const float* bvec,
                                           float* Out, float* scratch, float* mrs,
                                           const W44& wpre,
                                           int t, int cnt)
{
    const int c0 = (t & 63) * 4;
    const int r0 = (t >> 6) * 8;

    float y[8][4];
    #pragma unroll
    for (int r = 0; r < 8; r++)
        #pragma unroll
        for (int j = 0; j < 4; j++) y[r][j] = 0.f;

    if (r0 < cnt) {
        u64 acc[4][4];
        #pragma unroll
        for (int p = 0; p < 4; p++)
            #pragma unroll
            for (int j = 0; j < 4; j++) acc[p][j] = 0ull;

        const float* Wp = W + c0;

        #pragma unroll UNR
        for (int k0 = 0; k0 < K; k0 += 4) {
            const int sx = SWIN ? swz(k0) : 0;       // immediate when unrolled
            const int ra = r0 ^ sx;
            const int rb = (r0 + 4) ^ sx;

            float4 wv[4];
            if (k0 == 0) {                            // compile-time per instance
                wv[0] = wpre.a; wv[1] = wpre.b; wv[2] = wpre.c; wv[3] = wpre.d;
            } else {
                #pragma unroll
                for (int j = 0; j < 4; j++)
                    wv[j] = __ldcg((const float4*)(Wp + (k0 + j) * HH));
            }

            #pragma unroll
            for (int j = 0; j < 4; j++) {
                const int k = k0 + j;
                const double2 xa = *(const double2*)(In + k * TILE + ra);
                const double2 xb = *(const double2*)(In + k * TILE + rb);
                u64 xs[4];
                xs[0] = __double_as_longlong(xa.x); xs[1] = __double_as_longlong(xa.y);
                xs[2] = __double_as_longlong(xb.x); xs[3] = __double_as_longlong(xb.y);
                u64 w2[4] = { dup2(wv[j].x), dup2(wv[j].y), dup2(wv[j].z), dup2(wv[j].w) };
                #pragma unroll
                for (int p = 0; p < 4; p++)
                    #pragma unroll
                    for (int q = 0; q < 4; q++)
                        acc[p][q] = ffma2(xs[p], w2[q], acc[p][q]);
            }
        }

        #pragma unroll
        for (int j = 0; j < 4; j++) {
            const u64 b2 = dup2(bias[c0 + j]);
            #pragma unroll
            for (int p = 0; p < 4; p++) {
                const float2 f = unpack2(fadd2(acc[p][j], b2));
                y[2 * p][j]     = f.x;
                y[2 * p + 1][j] = f.y;
            }
        }
    }

    // per-thread 4-col partials for each of its 8 rows (zeros for dead rows).
    #pragma unroll
    for (int r = 0; r < 8; r++) {
        const float s  = (y[r][0] + y[r][1]) + (y[r][2] + y[r][3]);
        const float ss = (y[r][0] * y[r][0] + y[r][1] * y[r][1]) +
                         (y[r][2] * y[r][2] + y[r][3] * y[r][3]);
        *(float2*)(scratch + ((r0 + r) * 64 + (t & 63)) * 2) = make_float2(s, ss);
    }
    __syncthreads();   // sync-B: partials visible; all mainloop In reads done

    {
        const int row = t >> 3, seg = t & 7;
        float S = 0.f, SS = 0.f;
        #pragma unroll
        for (int i = 0; i < 8; i++) {
            const float2 p = *(const float2*)(scratch + (row * 64 + seg * 8 + i) * 2);
            S += p.x; SS += p.y;
        }
        #pragma unroll
        for (int o = 1; o < 8; o <<= 1) {
            S  += __shfl_xor_sync(0xffffffffu, S,  o);
            SS += __shfl_xor_sync(0xffffffffu, SS, o);
        }
        if (seg == 0) {
            const float m = S * (1.f / 256.f);
            const float var = SS * (1.f / 256.f) - m * m;
            *(float2*)(mrs + row * 2) = make_float2(m, rsqrtf(fmaxf(var, 0.f) + 1e-5f));
        }
    }
    __syncthreads();   // sync-C: mrs ready; scratch reads done

    const float4 gv = *(const float4*)(g + c0);
    const float4 bv = *(const float4*)(bvec + c0);
    #pragma unroll
    for (int q = 0; q < 4; q++) {
        const float4 mm = *(const float4*)(mrs + (r0 + 2 * q) * 2);  // rows 2q,2q+1
        y[2*q][0]   = fmaxf((y[2*q][0]   - mm.x) * mm.y * gv.x + bv.x, 0.f);
        y[2*q][1]   = fmaxf((y[2*q][1]   - mm.x) * mm.y * gv.y + bv.y, 0.f);
        y[2*q][2]   = fmaxf((y[2*q][2]   - mm.x) * mm.y * gv.z + bv.z, 0.f);
        y[2*q][3]   = fmaxf((y[2*q][3]   - mm.x) * mm.y * gv.w + bv.w, 0.f);
        y[2*q+1][0] = fmaxf((y[2*q+1][0] - mm.z) * mm.w * gv.x + bv.x, 0.f);
        y[2*q+1][1] = fmaxf((y[2*q+1][1] - mm.z) * mm.w * gv.y + bv.y, 0.f);
        y[2*q+1][2] = fmaxf((y[2*q+1][2] - mm.z) * mm.w * gv.z + bv.z, 0.f);
        y[2*q+1][3] = fmaxf((y[2*q+1][3] - mm.z) * mm.w * gv.w + bv.w, 0.f);
    }
    {
        const int so = swz(c0);                 // (c0+j)>>2 == t&63 for j<4
        const int ra = r0 ^ so;
        const int rb = (r0 + 4) ^ so;
        #pragma unroll
        for (int j = 0; j < 4; j++) {
            *(float4*)(Out + (c0 + j) * TILE + ra) =
                make_float4(y[0][j], y[1][j], y[2][j], y[3][j]);
            *(float4*)(Out + (c0 + j) * TILE + rb) =
                make_float4(y[4][j], y[5][j], y[6][j], y[7][j]);
        }
    }
    // NO trailing sync — caller synchronizes before Out is read.
}

// ---------- GEMM: In^T[K][32] @ W[K][128] -> Out^T[128][32], +bias, ReLU ----------
// thread tile: 8 rows (4 pairs) x 2 cols. Weights via __ldcg. Output swizzled.
// No trailing sync (unchanged contract: caller syncs after).
template<int K, bool SWIN, int UNR>
__device__ __forceinline__ void gemm_to128_relu(const float* In, const float* __restrict__ W,
                                                const float* __restrict__ bias, float* Out, int t)
{
    const int c0 = (t & 63) * 2;
    const int r0 = (t >> 6) * 8;
    u64 acc[4][2];
    #pragma unroll
    for (int p = 0; p < 4; p++) { acc[p][0] = 0ull; acc[p][1] = 0ull; }

    const float* Wp = W + c0;

    #pragma unroll UNR
    for (int k0 = 0; k0 < K; k0 += 4) {
        const int sx = SWIN ? swz(k0) : 0;
        const int ra = r0 ^ sx;
        const int rb = (r0 + 4) ^ sx;

        float2 wv[4];
        #pragma unroll
        for (int j = 0; j < 4; j++)
            wv[j] = __ldcg((const float2*)(Wp + (k0 + j) * 128));

        #pragma unroll
        for (int j = 0; j < 4; j++) {
            const int k = k0 + j;
            const double2 xa = *(const double2*)(In + k * TILE + ra);
            const double2 xb = *(const double2*)(In + k * TILE + rb);
            u64 xs[4];
            xs[0] = __double_as_longlong(xa.x); xs[1] = __double_as_longlong(xa.y);
            xs[2] = __double_as_longlong(xb.x); xs[3] = __double_as_longlong(xb.y);
            const u64 w0 = dup2(wv[j].x);
            const u64 w1 = dup2(wv[j].y);
            #pragma unroll
            for (int p = 0; p < 4; p++) {
                acc[p][0] = ffma2(xs[p], w0, acc[p][0]);
                acc[p][1] = ffma2(xs[p], w1, acc[p][1]);
            }
        }
    }

    const float2 bb = *(const float2*)(bias + c0);
    const int so = swz(c0);
    const int ra = r0 ^ so;
    const int rb = (r0 + 4) ^ so;
    #pragma unroll
    for (int j = 0; j < 2; j++) {
        const u64 b2 = dup2(j ? bb.y : bb.x);
        float o[8];
        #pragma unroll
        for (int p = 0; p < 4; p++) {
            const float2 f = unpack2(fadd2(acc[p][j], b2));
            o[2*p]   = fmaxf(f.x, 0.f);
            o[2*p+1] = fmaxf(f.y, 0.f);
        }
        *(float4*)(Out + (c0 + j) * TILE + ra) = make_float4(o[0], o[1], o[2], o[3]);
        *(float4*)(Out + (c0 + j) * TILE + rb) = make_float4(o[4], o[5], o[6], o[7]);
    }
}

__global__ void __launch_bounds__(NT, 3) moe_fused_kernel(
    const float* __restrict__ state,
    const float* __restrict__ rW1, const float* __restrict__ rb1,
    const float* __restrict__ rW2, const float* __restrict__ rb2,
    const float* __restrict__ eW1, const float* __restrict__ eb1,
    const float* __restrict__ eg1, const float* __restrict__ ebt1,
    const float* __restrict__ eW2, const float* __restrict__ eb2,
    const float* __restrict__ eg2, const float* __restrict__ ebt2,
    const float* __restrict__ eW3, const float* __restrict__ eb3,
    const float* __restrict__ vW1, const float* __restrict__ vb1,
    const float* __restrict__ vg,  const float* __restrict__ vbt,
    const float* __restrict__ vW2, const float* __restrict__ vb2,
    const float* __restrict__ vW3, const float* __restrict__ vb3,
    float* __restrict__ out)
{
    extern __shared__ float sm[];
    float* XsT    = sm;                   // [44][32] (linear, no swizzle)
    float* A1     = sm + OFF_A1;          // [256][32] swizzled; low 1408 stages XcT
    float* A2     = sm + OFF_A2;          // [256][32] swizzled; upper half = LN scratch
    float* lnscr  = A2 + 4096;            // LN partials scratch (A2 upper half)
    float* red    = sm + OFF_RED;         // [512] -> mixbuf[32][16] in expert phase
    float* mrs    = sm + OFF_MRS;         // [64]
    float* lg     = sm + OFF_LG;          // [128] logits -> int scratch
    int*   glist  = (int*)(sm + OFF_GLIST); // [128]
    float* gcomb  = sm + OFF_GCOMB;       // [128]

    int* lgI  = (int*)lg;
    int* cnt  = lgI;        // [4]
    int* goff = lgI + 4;    // [5]
    int* cur  = lgI + 9;    // [4]
    int* ggrp = lgI + 13;   // [16]

    const int t = threadIdx.x;
    const int c0g = (t & 63) * 4;   // gemm256 column base for this thread
    const bool is_value = (blockIdx.x >= NTILES);   // split schedule
    const int tileIdx = is_value ? (blockIdx.x - NTILES) : blockIdx.x;
    const int row0 = tileIdx * TILE;

    // ---- load state tile transposed: XsT[k][r] ----
    for (int i = t; i < TILE * DD; i += NT) {
        const int r = i / DD, k = i - r * DD;
        XsT[k * TILE + r] = state[(size_t)row0 * DD + i];
    }
    // prefetch the value net's first weight block in the shadow of the sync
    W44 wp;
    if (is_value) wp = pref4(vW1 + c0g);
    __syncthreads();

    if (is_value) {
        // ======== VALUE PATH ========
        gemm256_ln<DD, false, 16>(XsT, vW1, vb1, vg, vbt, A1, lnscr, mrs, wp, t, TILE);
        __syncthreads();   // A1 ready
        gemm_to128_relu<HH, true, 8>(A1, vW2, vb2, A2, t);
        __syncthreads();
        {   // value = v2 @ vW3 + vb3 (A2 is swizzled)
            const int r = t & 31, kg = t >> 5;
            float s = 0.f;
            #pragma unroll
            for (int i = 0; i < 16; i++) {
                const int k = kg * 16 + i;
                s = fmaf(A2[k * TILE + (r ^ swz(k))], vW3[k], s);
            }
            red[kg * 32 + r] = s;
        }
        __syncthreads();
        if (t < 32) {
            float S = 0.f;
            #pragma unroll
            for (int j = 0; j < 8; j++) S += red[j * 32 + t];
            out[(size_t)NB * 16 + row0 + t] = S + vb3[0];
        }
        return;
    }

    // ======== ROUTER + EXPERT PATH ========
    gemm_to128_relu<DD, false, 2>(XsT, rW1, rb1, A2, t);   // A2 lower half, swizzled
    __syncthreads();

    // router logits partials (A2 swizzled)
    if (t < 128) {
        const int r = t & 31, kg = t >> 5;
        float a0 = 0.f, a1 = 0.f, a2 = 0.f, a3 = 0.f;
        #pragma unroll 8
        for (int i = 0; i < 32; i++) {
            const int k = kg * 32 + i;
            const float x = A2[k * TILE + (r ^ swz(k))];
            a0 = fmaf(x, rW2[k * 4 + 0], a0);
            a1 = fmaf(x, rW2[k * 4 + 1], a1);
            a2 = fmaf(x, rW2[k * 4 + 2], a2);
            a3 = fmaf(x, rW2[k * 4 + 3], a3);
        }
        red[(0 * 4 + kg) * 32 + r] = a0;
        red[(1 * 4 + kg) * 32 + r] = a1;
        red[(2 * 4 + kg) * 32 + r] = a2;
        red[(3 * 4 + kg) * 32 + r] = a3;
    }
    __syncthreads();

    // reduce logits into registers of threads t<32 (logit e for row t)
    float myLogit[4];
    if (t < 32) {
        #pragma unroll
        for (int e = 0; e < 4; e++) {
            float acc = rb2[e];
            #pragma unroll
            for (int kg = 0; kg < 4; kg++) acc += red[(e * 4 + kg) * 32 + t];
            myLogit[e] = acc;
        }
    }
    if (t < 4) cnt[t] = 0;
    __syncthreads();

    // softmax, top-2, counts; router_probs out
    int myI0 = 0, myI1 = 0;
    float myW0 = 0.f, myW1 = 0.f;
    if (t < TILE) {
        float l[4];
        #pragma unroll
        for (int e = 0; e < 4; e++) l[e] = myLogit[e];
        const float m = fmaxf(fmaxf(l[0], l[1]), fmaxf(l[2], l[3]));
        float p[4], s = 0.f;
        #pragma unroll
        for (int e = 0; e < 4; e++) { p[e] = expf(l[e] - m); s += p[e]; }
        const float inv = 1.f / s;
        #pragma unroll
        for (int e = 0; e < 4; e++) p[e] *= inv;

        const size_t rbase = (size_t)NB * 17 + (size_t)(row0 + t) * 4;
        #pragma unroll
        for (int e = 0; e < 4; e++) out[rbase + e] = p[e];

        int i0 = 0; float v0 = p[0];
        #pragma unroll
        for (int e = 1; e < 4; e++) if (p[e] > v0) { v0 = p[e]; i0 = e; }
        int i1 = -1; float v1 = -1.f;
        #pragma unroll
        for (int e = 0; e < 4; e++) if (e != i0 && p[e] > v1) { v1 = p[e]; i1 = e; }
        const float denom = 1.f / (v0 + v1 + 1e-8f);
        myI0 = i0; myI1 = i1;
        myW0 = v0 * denom; myW1 = v1 * denom;
        atomicAdd(&cnt[i0], 1);
        atomicAdd(&cnt[i1], 1);
    }
    // zero mixbuf (= red); logits reads of red completed before previous sync
    for (int i = t; i < 512; i += NT) red[i] = 0.f;
    float* mixbuf = red;   // [32 rows][16 cols]
    __syncthreads();

    // prefix offsets of padded segments; cursors; ggrp init
    if (t == 0) {
        int off = 0;
        #pragma unroll
        for (int e = 0; e < 4; e++) {
            goff[e] = off;
            cur[e] = off;
            off += (cnt[e] + 7) & ~7;
        }
        goff[4] = off;   // tot_pad
        #pragma unroll
        for (int j = 0; j < 16; j++) ggrp[j] = 0;
    }
    __syncthreads();

    // claim slots; pad-fill; ggrp fill
    if (t < TILE) {
        const int s0 = atomicAdd(&cur[myI0], 1);
        glist[s0] = t; gcomb[s0] = myW0;
        const int s1 = atomicAdd(&cur[myI1], 1);
        glist[s1] = t; gcomb[s1] = myW1;
    } else if (t < 160) {
        const int e = (t - 32) >> 5, j = (t - 32) & 31;
        const int c = cnt[e], cp = (c + 7) & ~7;
        if (j >= c && j < cp) {
            glist[goff[e] + j] = 32;   // dead-row marker
            gcomb[goff[e] + j] = 0.f;
        }
    } else if (t < 176) {
        const int gidx = t - 160;
        const int rowbase = gidx * 8;
        if (rowbase < goff[4]) {
            int e = 0;
            #pragma unroll
            for (int q = 1; q < 4; q++) if (rowbase >= goff[q]) e = q;
            ggrp[gidx] = e;
        }
    }
    __syncthreads();

    const int tot_pad = goff[4];
    const int nchunk = (tot_pad + 31) >> 5;

    const int ec  = t & 15;
    const int ep  = t >> 4;
    const int r0g = (t >> 6) * 8;

    // pre-gather chunk 0 into A1[0:1408), stored SWIZZLED
    {
        const int c0n = min(32, tot_pad);
        for (int i = t; i < DD * TILE; i += NT) {
            const int r = i & 31, k = i >> 5;
            if (r < c0n) {
                const int o = glist[r];
                A1[k * TILE + (r ^ swz(k))] = (o < 32) ? XsT[k * TILE + o] : 0.f;
            }
        }
    }

    // prefetch G1 weights for chunk 0 (ge known; hidden by loop-start sync)
    int ge = ggrp[r0g >> 3];
    if (r0g < min(32, tot_pad))
        wp = pref4(eW1 + (size_t)ge * DD * HH + c0g);

    // ---- experts: single compacted stream, <= 3 chunks ----
    for (int g = 0; g < nchunk; g++) {
        __syncthreads();   // S0: gather(g) visible; prior G3 A2-reads done; lnscr free
        const int base = g * 32;
        const int ccnt = min(32, tot_pad - base);   // multiple of 8

        // G1: In = XcT staged in A1 (swizzled; aliases Out — safe per internal syncs)
        gemm256_ln<DD, true, 16>(A1, eW1 + (size_t)ge * DD * HH, eb1 + ge * HH,
                                 eg1 + ge * HH, ebt1 + ge * HH, A1, lnscr, mrs,
                                 wp, t, ccnt);
        // prefetch G2's first weight block in the shadow of S1
        W44 wp2;
        if (r0g < ccnt)
            wp2 = pref4(eW2 + (size_t)ge * HH * HH + c0g);
        __syncthreads();   // S1: A1 (G1 out) ready
        // G2: In = A1, Out = A2; scratch = lnscr (A2 upper half)
        gemm256_ln<HH, true, 8>(A1, eW2 + (size_t)ge * HH * HH, eb2 + ge * HH,
                                eg2 + ge * HH, ebt2 + ge * HH, A2, lnscr, mrs,
                                wp2, t, ccnt);
        // prefetch next chunk's G1 weights in the shadow of S2
        if (g + 1 < nchunk) {
            const int geN = ggrp[((base + 32) + r0g) >> 3];
            if (r0g < tot_pad - base - 32 || true) {   // ggrp defaults to 0; guard via rows below
                if (r0g < min(32, tot_pad - base - 32))
                    wp = pref4(eW1 + (size_t)geN * DD * HH + c0g);
            }
            ge = geN;
        }
        __syncthreads();   // S2: A2 (G2 out) ready

        // gather chunk g+1 into A1[0:1408) (swizzled) — overlaps GEMM3
        if (g + 1 < nchunk) {
            const int nb = base + 32;
            const int ncn = min(32, tot_pad - nb);
            for (int i = t; i < DD * TILE; i += NT) {
                const int r = i & 31, k = i >> 5;
                if (r < ncn) {
                    const int o = glist[nb + r];
                    A1[k * TILE + (r ^ swz(k))] = (o < 32) ? XsT[k * TILE + o] : 0.f;
                }
            }
        }

        // GEMM3 on active row pairs; expert per row-pair (half-warp uniform)
        if (2 * ep < ccnt) {
            const int e3 = ggrp[(base + 2 * ep) >> 3];
            const float* W3p = eW3 + (size_t)e3 * HH * 16 + ec;
            u64 a2 = 0ull;
            #pragma unroll 8
            for (int k0 = 0; k0 < HH; k0 += 4) {
                const int rp = (2 * ep) ^ swz(k0);   // immediate offsets when unrolled
                float wv[4];
                #pragma unroll
                for (int j = 0; j < 4; j++) wv[j] = __ldcg(W3p + (k0 + j) * 16);
                #pragma unroll
                for (int j = 0; j < 4; j++) {
                    const u64 x = __double_as_longlong(
                        *(const double*)(A2 + (k0 + j) * TILE + rp));
                    a2 = ffma2(x, dup2(wv[j]), a2);
                }
            }
            const u64 b2 = dup2(eb3[e3 * 16 + ec]);
            const float2 y2 = unpack2(fadd2(a2, b2));
            const int o0 = glist[base + 2 * ep];
            const int o1 = glist[base + 2 * ep + 1];
            const float cw0 = gcomb[base + 2 * ep];
            const float cw1 = gcomb[base + 2 * ep + 1];
            // same orig row may appear twice within a chunk -> atomic (2-add fp is commutative)
            if (o0 < 32) atomicAdd(&mixbuf[o0 * 16 + ec], cw0 * y2.x);
            if (o1 < 32) atomicAdd(&mixbuf[o1 * 16 + ec], cw1 * y2.y);
        }
    }
    __syncthreads();   // mixbuf complete

    // ---- epilogue: alpha / beta ----
    {
        const float mA = mixbuf[(2 * ep) * 16 + ec];
        const float mB = mixbuf[(2 * ep + 1) * 16 + ec];
        const float oA = softplus1(mA);
        const float oB = softplus1(mB);
        const size_t rowA = row0 + 2 * ep;
        const size_t rowB = rowA + 1;
        if (ec < AA) {
            out[rowA * AA + ec] = oA;
            out[rowB * AA + ec] = oB;
        } else {
            out[(size_t)NB * AA + rowA * AA + (ec - AA)] = oA;
            out[(size_t)NB * AA + rowB * AA + (ec - AA)] = oB;
        }
    }
}

extern "C" void kernel_launch(void* const* d_in, const int* in_sizes, int n_in,
                              void* d_out, int out_size) {
    const float* state = (const float*)d_in[0];
    const float* rW1   = (const float*)d_in[1];
    const float* rb1   = (const float*)d_in[2];
    const float* rW2   = (const float*)d_in[3];
    const float* rb2   = (const float*)d_in[4];
    const float* eW1   = (const float*)d_in[5];
    const float* eb1   = (const float*)d_in[6];
    const float* eg1   = (const float*)d_in[7];
    const float* ebt1  = (const float*)d_in[8];
    const float* eW2   = (const float*)d_in[9];
    const float* eb2   = (const float*)d_in[10];
    const float* eg2   = (const float*)d_in[11];
    const float* ebt2  = (const float*)d_in[12];
    const float* eW3   = (const float*)d_in[13];
    const float* eb3   = (const float*)d_in[14];
    const float* vW1   = (const float*)d_in[15];
    const float* vb1   = (const float*)d_in[16];
    const float* vg    = (const float*)d_in[17];
    const float* vbt   = (const float*)d_in[18];
    const float* vW2   = (const float*)d_in[19];
    const float* vb2   = (const float*)d_in[20];
    const float* vW3   = (const float*)d_in[21];
    const float* vb3   = (const float*)d_in[22];
    float* out = (float*)d_out;

    cudaFuncSetAttribute(moe_fused_kernel,
                         cudaFuncAttributeMaxDynamicSharedMemorySize, SMEM_BYTES);

    moe_fused_kernel<<<2 * NTILES, NT, SMEM_BYTES>>>(
        state, rW1, rb1, rW2, rb2,
        eW1, eb1, eg1, ebt1, eW2, eb2, eg2, ebt2, eW3, eb3,
        vW1, vb1, vg, vbt, vW2, vb2, vW3, vb3, out);
}

// round 17
// speedup vs baseline: 1.0479x; 1.0479x over previous
#include <cuda_runtime.h>
#include <math.h>

typedef unsigned long long u64;

#define NB   65536
#define DD   44
#define HH   256
#define EE   4
#define AA   8
#define TILE 32
#define NT   256
#define NTILES (NB / TILE)

// dynamic smem layout (floats) — activation buffers TRANSPOSED: buf[feature][row]
#define OFF_A1    (TILE*DD)               // XsT: [0,1408)
#define OFF_A2    (OFF_A1 + HH*TILE)      // A1:  [1408,9600)  (XcT staged in A1[0:1408))
#define OFF_RED   (OFF_A2 + HH*TILE)      // A2:  [9600,17792); upper half doubles as LN scratch
#define OFF_MRS   (OFF_RED + 512)
#define OFF_LG    (OFF_MRS + 64)          // lg[128] -> int scratch in expert phase
#define OFF_GLIST (OFF_LG + TILE*EE)      // int glist[128]
#define OFF_GCOMB (OFF_GLIST + TILE*EE)   // float gcomb[128]
#define OFF_ECNT  (OFF_GCOMB + TILE*EE)
#define SMEM_FLOATS (OFF_ECNT + 8)
#define SMEM_BYTES  (SMEM_FLOATS * 4)

// Row swizzle inside A1/A2 (bank de-conflict): feature k's row r lives at
// slot r ^ swz(k). swz is a multiple of 4 XORed into row bits 2..4.
// Fully unrolled loops fold swz to immediates.
__device__ __forceinline__ int swz(int k) { return 4 * ((k >> 2) & 7); }

// ---------- packed f32x2 helpers ----------
__device__ __forceinline__ u64 ffma2(u64 a, u64 b, u64 c) {
    u64 d;
    asm("fma.rn.f32x2 %0, %1, %2, %3;" : "=l"(d) : "l"(a), "l"(b), "l"(c));
    return d;
}
__device__ __forceinline__ u64 fadd2(u64 a, u64 b) {
    u64 d;
    asm("add.rn.f32x2 %0, %1, %2;" : "=l"(d) : "l"(a), "l"(b));
    return d;
}
__device__ __forceinline__ u64 dup2(float w) {
    u64 d; unsigned int ui = __float_as_uint(w);
    asm("mov.b64 %0, {%1, %1};" : "=l"(d) : "r"(ui));
    return d;
}
__device__ __forceinline__ float2 unpack2(u64 a) {
    float2 f;
    asm("mov.b64 {%0, %1}, %2;" : "=f"(f.x), "=f"(f.y) : "l"(a));
    return f;
}
__device__ __forceinline__ float softplus1(float x) {
    return fmaxf(x, 0.f) + log1pf(expf(-fabsf(x))) + 1.f;
}

// ---------- fused GEMM + LayerNorm + ReLU, row-sparse ----------
// Out^T[256][32] = relu(LN(In^T[K][32] @ W[K][256] + bias) * g + b)
// thread tile: 8 rows (4 packed pairs) x 4 cols. K % 4 == 0.
// Weights via __ldcg (L2 streaming). SWIN: input row-swizzled (A1/A2) or not
// (XsT). Output ALWAYS stored swizzled. UNR: k0-loop unroll factor; >= K/4
// fully unrolls so all smem offsets fold to immediates.
// PRECONDITIONS: scratch must NOT alias In (pre-fenced); In may alias Out.
// Row-groups with r0 >= cnt skip the mainloop (cnt % 8 == 0 -> warp-uniform).
// Contains 3 __syncthreads (incl. trailing one: Out ready on return).
template<int K, bool SWIN, int UNR>
__device__ __forceinline__ void gemm256_ln(const float* In, const float* W,
                                           const float* bias,
                                           const float* g,
                                           const float* bvec,
                                           float* Out, float* scratch, float* mrs,
                                           int t, int cnt)
{
    const int c0 = (t & 63) * 4;
    const int r0 = (t >> 6) * 8;

    float y[8][4];
    #pragma unroll
    for (int r = 0; r < 8; r++)
        #pragma unroll
        for (int j = 0; j < 4; j++) y[r][j] = 0.f;

    if (r0 < cnt) {
        u64 acc[4][4];
        #pragma unroll
        for (int p = 0; p < 4; p++)
            #pragma unroll
            for (int j = 0; j < 4; j++) acc[p][j] = 0ull;

        const float* Wp = W + c0;

        #pragma unroll UNR
        for (int k0 = 0; k0 < K; k0 += 4) {
            const int sx = SWIN ? swz(k0) : 0;       // immediate when unrolled
            const int ra = r0 ^ sx;
            const int rb = (r0 + 4) ^ sx;

            float4 wv[4];
            #pragma unroll
            for (int j = 0; j < 4; j++)
                wv[j] = __ldcg((const float4*)(Wp + (k0 + j) * HH));

            #pragma unroll
            for (int j = 0; j < 4; j++) {
                const int k = k0 + j;
                const double2 xa = *(const double2*)(In + k * TILE + ra);
                const double2 xb = *(const double2*)(In + k * TILE + rb);
                u64 xs[4];
                xs[0] = __double_as_longlong(xa.x); xs[1] = __double_as_longlong(xa.y);
                xs[2] = __double_as_longlong(xb.x); xs[3] = __double_as_longlong(xb.y);
                u64 w2[4] = { dup2(wv[j].x), dup2(wv[j].y), dup2(wv[j].z), dup2(wv[j].w) };
                #pragma unroll
                for (int p = 0; p < 4; p++)
                    #pragma unroll
                    for (int q = 0; q < 4; q++)
                        acc[p][q] = ffma2(xs[p], w2[q], acc[p][q]);
            }
        }

        #pragma unroll
        for (int j = 0; j < 4; j++) {
            const u64 b2 = dup2(bias[c0 + j]);
            #pragma unroll
            for (int p = 0; p < 4; p++) {
                const float2 f = unpack2(fadd2(acc[p][j], b2));
                y[2 * p][j]     = f.x;
                y[2 * p + 1][j] = f.y;
            }
        }
    }

    // per-thread 4-col partials for each of its 8 rows (zeros for dead rows).
    #pragma unroll
    for (int r = 0; r < 8; r++) {
        const float s  = (y[r][0] + y[r][1]) + (y[r][2] + y[r][3]);
        const float ss = (y[r][0] * y[r][0] + y[r][1] * y[r][1]) +
                         (y[r][2] * y[r][2] + y[r][3] * y[r][3]);
        *(float2*)(scratch + ((r0 + r) * 64 + (t & 63)) * 2) = make_float2(s, ss);
    }
    __syncthreads();   // sync-B: partials visible; all mainloop In reads done

    {
        const int row = t >> 3, seg = t & 7;
        float S = 0.f, SS = 0.f;
        #pragma unroll
        for (int i = 0; i < 8; i++) {
            const float2 p = *(const float2*)(scratch + (row * 64 + seg * 8 + i) * 2);
            S += p.x; SS += p.y;
        }
        #pragma unroll
        for (int o = 1; o < 8; o <<= 1) {
            S  += __shfl_xor_sync(0xffffffffu, S,  o);
            SS += __shfl_xor_sync(0xffffffffu, SS, o);
        }
        if (seg == 0) {
            const float m = S * (1.f / 256.f);
            const float var = SS * (1.f / 256.f) - m * m;
            *(float2*)(mrs + row * 2) = make_float2(m, rsqrtf(fmaxf(var, 0.f) + 1e-5f));
        }
    }
    __syncthreads();   // sync-C: mrs ready; scratch reads done

    const float4 gv = *(const float4*)(g + c0);
    const float4 bv = *(const float4*)(bvec + c0);
    #pragma unroll
    for (int q = 0; q < 4; q++) {
        const float4 mm = *(const float4*)(mrs + (r0 + 2 * q) * 2);  // rows 2q,2q+1
        y[2*q][0]   = fmaxf((y[2*q][0]   - mm.x) * mm.y * gv.x + bv.x, 0.f);
        y[2*q][1]   = fmaxf((y[2*q][1]   - mm.x) * mm.y * gv.y + bv.y, 0.f);
        y[2*q][2]   = fmaxf((y[2*q][2]   - mm.x) * mm.y * gv.z + bv.z, 0.f);
        y[2*q][3]   = fmaxf((y[2*q][3]   - mm.x) * mm.y * gv.w + bv.w, 0.f);
        y[2*q+1][0] = fmaxf((y[2*q+1][0] - mm.z) * mm.w * gv.x + bv.x, 0.f);
        y[2*q+1][1] = fmaxf((y[2*q+1][1] - mm.z) * mm.w * gv.y + bv.y, 0.f);
        y[2*q+1][2] = fmaxf((y[2*q+1][2] - mm.z) * mm.w * gv.z + bv.z, 0.f);
        y[2*q+1][3] = fmaxf((y[2*q+1][3] - mm.z) * mm.w * gv.w + bv.w, 0.f);
    }
    {
        const int so = swz(c0);                 // (c0+j)>>2 == t&63 for j<4
        const int ra = r0 ^ so;
        const int rb = (r0 + 4) ^ so;
        #pragma unroll
        for (int j = 0; j < 4; j++) {
            *(float4*)(Out + (c0 + j) * TILE + ra) =
                make_float4(y[0][j], y[1][j], y[2][j], y[3][j]);
            *(float4*)(Out + (c0 + j) * TILE + rb) =
                make_float4(y[4][j], y[5][j], y[6][j], y[7][j]);
        }
    }
    __syncthreads();   // sync-D: Out ready
}

// ---------- GEMM: In^T[K][32] @ W[K][128] -> Out^T[128][32], +bias, ReLU ----------
// thread tile: 8 rows (4 pairs) x 2 cols. Weights via __ldcg. Output swizzled.
template<int K, bool SWIN, int UNR>
__device__ __forceinline__ void gemm_to128_relu(const float* In, const float* __restrict__ W,
                                                const float* __restrict__ bias, float* Out, int t)
{
    const int c0 = (t & 63) * 2;
    const int r0 = (t >> 6) * 8;
    u64 acc[4][2];
    #pragma unroll
    for (int p = 0; p < 4; p++) { acc[p][0] = 0ull; acc[p][1] = 0ull; }

    const float* Wp = W + c0;

    #pragma unroll UNR
    for (int k0 = 0; k0 < K; k0 += 4) {
        const int sx = SWIN ? swz(k0) : 0;
        const int ra = r0 ^ sx;
        const int rb = (r0 + 4) ^ sx;

        float2 wv[4];
        #pragma unroll
        for (int j = 0; j < 4; j++)
            wv[j] = __ldcg((const float2*)(Wp + (k0 + j) * 128));

        #pragma unroll
        for (int j = 0; j < 4; j++) {
            const int k = k0 + j;
            const double2 xa = *(const double2*)(In + k * TILE + ra);
            const double2 xb = *(const double2*)(In + k * TILE + rb);
            u64 xs[4];
            xs[0] = __double_as_longlong(xa.x); xs[1] = __double_as_longlong(xa.y);
            xs[2] = __double_as_longlong(xb.x); xs[3] = __double_as_longlong(xb.y);
            const u64 w0 = dup2(wv[j].x);
            const u64 w1 = dup2(wv[j].y);
            #pragma unroll
            for (int p = 0; p < 4; p++) {
                acc[p][0] = ffma2(xs[p], w0, acc[p][0]);
                acc[p][1] = ffma2(xs[p], w1, acc[p][1]);
            }
        }
    }

    const float2 bb = *(const float2*)(bias + c0);
    const int so = swz(c0);
    const int ra = r0 ^ so;
    const int rb = (r0 + 4) ^ so;
    #pragma unroll
    for (int j = 0; j < 2; j++) {
        const u64 b2 = dup2(j ? bb.y : bb.x);
        float o[8];
        #pragma unroll
        for (int p = 0; p < 4; p++) {
            const float2 f = unpack2(fadd2(acc[p][j], b2));
            o[2*p]   = fmaxf(f.x, 0.f);
            o[2*p+1] = fmaxf(f.y, 0.f);
        }
        *(float4*)(Out + (c0 + j) * TILE + ra) = make_float4(o[0], o[1], o[2], o[3]);
        *(float4*)(Out + (c0 + j) * TILE + rb) = make_float4(o[4], o[5], o[6], o[7]);
    }
}

__global__ void __launch_bounds__(NT, 3) moe_fused_kernel(
    const float* __restrict__ state,
    const float* __restrict__ rW1, const float* __restrict__ rb1,
    const float* __restrict__ rW2, const float* __restrict__ rb2,
    const float* __restrict__ eW1, const float* __restrict__ eb1,
    const float* __restrict__ eg1, const float* __restrict__ ebt1,
    const float* __restrict__ eW2, const float* __restrict__ eb2,
    const float* __restrict__ eg2, const float* __restrict__ ebt2,
    const float* __restrict__ eW3, const float* __restrict__ eb3,
    const float* __restrict__ vW1, const float* __restrict__ vb1,
    const float* __restrict__ vg,  const float* __restrict__ vbt,
    const float* __restrict__ vW2, const float* __restrict__ vb2,
    const float* __restrict__ vW3, const float* __restrict__ vb3,
    float* __restrict__ out)
{
    extern __shared__ float sm[];
    float* XsT    = sm;                   // [44][32] (linear, no swizzle)
    float* A1     = sm + OFF_A1;          // [256][32] swizzled; low 1408 stages XcT
    float* A2     = sm + OFF_A2;          // [256][32] swizzled; upper half = LN scratch
    float* lnscr  = A2 + 4096;            // LN partials scratch (A2 upper half)
    float* red    = sm + OFF_RED;         // [512] -> mixbuf[32][16] in expert phase
    float* mrs    = sm + OFF_MRS;         // [64]
    float* lg     = sm + OFF_LG;          // [128] logits -> int scratch
    int*   glist  = (int*)(sm + OFF_GLIST); // [128]
    float* gcomb  = sm + OFF_GCOMB;       // [128]

    int* lgI  = (int*)lg;
    int* cnt  = lgI;        // [4]
    int* goff = lgI + 4;    // [5]
    int* cur  = lgI + 9;    // [4]
    int* ggrp = lgI + 13;   // [16]

    const int t = threadIdx.x;
    const bool is_value = (blockIdx.x >= NTILES);   // split schedule (R10/R13)
    const int tileIdx = is_value ? (blockIdx.x - NTILES) : blockIdx.x;
    const int row0 = tileIdx * TILE;

    // ---- load state tile transposed: XsT[k][r] ----
    for (int i = t; i < TILE * DD; i += NT) {
        const int r = i / DD, k = i - r * DD;
        XsT[k * TILE + r] = state[(size_t)row0 * DD + i];
    }
    __syncthreads();

    if (is_value) {
        // ======== VALUE PATH ========
        gemm256_ln<DD, false, 16>(XsT, vW1, vb1, vg, vbt, A1, lnscr, mrs, t, TILE);
        gemm_to128_relu<HH, true, 8>(A1, vW2, vb2, A2, t);
        __syncthreads();
        {   // value = v2 @ vW3 + vb3 (A2 is swizzled)
            const int r = t & 31, kg = t >> 5;
            float s = 0.f;
            #pragma unroll
            for (int i = 0; i < 16; i++) {
                const int k = kg * 16 + i;
                s = fmaf(A2[k * TILE + (r ^ swz(k))], vW3[k], s);
            }
            red[kg * 32 + r] = s;
        }
        __syncthreads();
        if (t < 32) {
            float S = 0.f;
            #pragma unroll
            for (int j = 0; j < 8; j++) S += red[j * 32 + t];
            out[(size_t)NB * 16 + row0 + t] = S + vb3[0];
        }
        return;
    }

    // ======== ROUTER + EXPERT PATH ========
    gemm_to128_relu<DD, false, 16>(XsT, rW1, rb1, A2, t);   // A2 lower half, swizzled
    __syncthreads();

    // router logits partials (A2 swizzled)
    if (t < 128) {
        const int r = t & 31, kg = t >> 5;
        float a0 = 0.f, a1 = 0.f, a2 = 0.f, a3 = 0.f;
        #pragma unroll 8
        for (int i = 0; i < 32; i++) {
            const int k = kg * 32 + i;
            const float x = A2[k * TILE + (r ^ swz(k))];
            a0 = fmaf(x, rW2[k * 4 + 0], a0);
            a1 = fmaf(x, rW2[k * 4 + 1], a1);
            a2 = fmaf(x, rW2[k * 4 + 2], a2);
            a3 = fmaf(x, rW2[k * 4 + 3], a3);
        }
        red[(0 * 4 + kg) * 32 + r] = a0;
        red[(1 * 4 + kg) * 32 + r] = a1;
        red[(2 * 4 + kg) * 32 + r] = a2;
        red[(3 * 4 + kg) * 32 + r] = a3;
    }
    __syncthreads();

    // reduce logits into registers of threads t<32 (logit e for row t)
    float myLogit[4];
    if (t < 32) {
        #pragma unroll
        for (int e = 0; e < 4; e++) {
            float acc = rb2[e];
            #pragma unroll
            for (int kg = 0; kg < 4; kg++) acc += red[(e * 4 + kg) * 32 + t];
            myLogit[e] = acc;
        }
    }
    if (t < 4) cnt[t] = 0;
    __syncthreads();

    // softmax, top-2, counts; router_probs out
    int myI0 = 0, myI1 = 0;
    float myW0 = 0.f, myW1 = 0.f;
    if (t < TILE) {
        float l[4];
        #pragma unroll
        for (int e = 0; e < 4; e++) l[e] = myLogit[e];
        const float m = fmaxf(fmaxf(l[0], l[1]), fmaxf(l[2], l[3]));
        float p[4], s = 0.f;
        #pragma unroll
        for (int e = 0; e < 4; e++) { p[e] = expf(l[e] - m); s += p[e]; }
        const float inv = 1.f / s;
        #pragma unroll
        for (int e = 0; e < 4; e++) p[e] *= inv;

        const size_t rbase = (size_t)NB * 17 + (size_t)(row0 + t) * 4;
        #pragma unroll
        for (int e = 0; e < 4; e++) out[rbase + e] = p[e];

        int i0 = 0; float v0 = p[0];
        #pragma unroll
        for (int e = 1; e < 4; e++) if (p[e] > v0) { v0 = p[e]; i0 = e; }
        int i1 = -1; float v1 = -1.f;
        #pragma unroll
        for (int e = 0; e < 4; e++) if (e != i0 && p[e] > v1) { v1 = p[e]; i1 = e; }
        const float denom = 1.f / (v0 + v1 + 1e-8f);
        myI0 = i0; myI1 = i1;
        myW0 = v0 * denom; myW1 = v1 * denom;
        atomicAdd(&cnt[i0], 1);
        atomicAdd(&cnt[i1], 1);
    }
    // zero mixbuf (= red); logits reads of red completed before previous sync
    for (int i = t; i < 512; i += NT) red[i] = 0.f;
    float* mixbuf = red;   // [32 rows][16 cols]
    __syncthreads();

    // prefix offsets of padded segments; cursors; ggrp init
    if (t == 0) {
        int off = 0;
        #pragma unroll
        for (int e = 0; e < 4; e++) {
            goff[e] = off;
            cur[e] = off;
            off += (cnt[e] + 7) & ~7;
        }
        goff[4] = off;   // tot_pad
        #pragma unroll
        for (int j = 0; j < 16; j++) ggrp[j] = 0;
    }
    __syncthreads();

    // claim slots; pad-fill; ggrp fill
    if (t < TILE) {
        const int s0 = atomicAdd(&cur[myI0], 1);
        glist[s0] = t; gcomb[s0] = myW0;
        const int s1 = atomicAdd(&cur[myI1], 1);
        glist[s1] = t; gcomb[s1] = myW1;
    } else if (t < 160) {
        const int e = (t - 32) >> 5, j = (t - 32) & 31;
        const int c = cnt[e], cp = (c + 7) & ~7;
        if (j >= c && j < cp) {
            glist[goff[e] + j] = 32;   // dead-row marker
            gcomb[goff[e] + j] = 0.f;
        }
    } else if (t < 176) {
        const int gidx = t - 160;
        const int rowbase = gidx * 8;
        if (rowbase < goff[4]) {
            int e = 0;
            #pragma unroll
            for (int q = 1; q < 4; q++) if (rowbase >= goff[q]) e = q;
            ggrp[gidx] = e;
        }
    }
    __syncthreads();

    const int tot_pad = goff[4];
    const int nchunk = (tot_pad + 31) >> 5;

    const int ec  = t & 15;
    const int ep  = t >> 4;
    const int r0g = (t >> 6) * 8;

    // pre-gather chunk 0 into A1[0:1408), stored SWIZZLED
    {
        const int c0n = min(32, tot_pad);
        for (int i = t; i < DD * TILE; i += NT) {
            const int r = i & 31, k = i >> 5;
            if (r < c0n) {
                const int o = glist[r];
                A1[k * TILE + (r ^ swz(k))] = (o < 32) ? XsT[k * TILE + o] : 0.f;
            }
        }
    }

    // ---- experts: single compacted stream, <= 3 chunks ----
    for (int g = 0; g < nchunk; g++) {
        __syncthreads();   // gather(g) visible; prior G3 A2-reads done (protects lnscr too)
        const int base = g * 32;
        const int ccnt = min(32, tot_pad - base);   // multiple of 8

        // this thread's 8 rows all belong to one expert group
        const int ge = ggrp[(base + r0g) >> 3];

        // G1: In = XcT staged in A1 (swizzled; aliases Out — safe per internal syncs)
        gemm256_ln<DD, true, 16>(A1, eW1 + (size_t)ge * DD * HH, eb1 + ge * HH,
                                 eg1 + ge * HH, ebt1 + ge * HH, A1, lnscr, mrs, t, ccnt);
        // G2: In = A1, Out = A2; scratch = lnscr (A2 upper half)
        gemm256_ln<HH, true, 8>(A1, eW2 + (size_t)ge * HH * HH, eb2 + ge * HH,
                                eg2 + ge * HH, ebt2 + ge * HH, A2, lnscr, mrs, t, ccnt);

        // gather chunk g+1 into A1[0:1408) (swizzled) — overlaps GEMM3
        if (g + 1 < nchunk) {
            const int nb = base + 32;
            const int ncn = min(32, tot_pad - nb);
            for (int i = t; i < DD * TILE; i += NT) {
                const int r = i & 31, k = i >> 5;
                if (r < ncn) {
                    const int o = glist[nb + r];
                    A1[k * TILE + (r ^ swz(k))] = (o < 32) ? XsT[k * TILE + o] : 0.f;
                }
            }
        }

        // GEMM3 on active row pairs; expert per row-pair (half-warp uniform)
        if (2 * ep < ccnt) {
            const int e3 = ggrp[(base + 2 * ep) >> 3];
            const float* W3p = eW3 + (size_t)e3 * HH * 16 + ec;
            u64 a2 = 0ull;
            #pragma unroll 8
            for (int k0 = 0; k0 < HH; k0 += 4) {
                const int rp = (2 * ep) ^ swz(k0);   // immediate offsets when unrolled
                float wv[4];
                #pragma unroll
                for (int j = 0; j < 4; j++) wv[j] = __ldcg(W3p + (k0 + j) * 16);
                #pragma unroll
                for (int j = 0; j < 4; j++) {
                    const u64 x = __double_as_longlong(
                        *(const double*)(A2 + (k0 + j) * TILE + rp));
                    a2 = ffma2(x, dup2(wv[j]), a2);
                }
            }
            const u64 b2 = dup2(eb3[e3 * 16 + ec]);
            const float2 y2 = unpack2(fadd2(a2, b2));
            const int o0 = glist[base + 2 * ep];
            const int o1 = glist[base + 2 * ep + 1];
            const float cw0 = gcomb[base + 2 * ep];
            const float cw1 = gcomb[base + 2 * ep + 1];
            // same orig row may appear twice within a chunk -> atomic (2-add fp is commutative)
            if (o0 < 32) atomicAdd(&mixbuf[o0 * 16 + ec], cw0 * y2.x);
            if (o1 < 32) atomicAdd(&mixbuf[o1 * 16 + ec], cw1 * y2.y);
        }
    }
    __syncthreads();   // mixbuf complete

    // ---- epilogue: alpha / beta ----
    {
        const float mA = mixbuf[(2 * ep) * 16 + ec];
        const float mB = mixbuf[(2 * ep + 1) * 16 + ec];
        const float oA = softplus1(mA);
        const float oB = softplus1(mB);
        const size_t rowA = row0 + 2 * ep;
        const size_t rowB = rowA + 1;
        if (ec < AA) {
            out[rowA * AA + ec] = oA;
            out[rowB * AA + ec] = oB;
        } else {
            out[(size_t)NB * AA + rowA * AA + (ec - AA)] = oA;
            out[(size_t)NB * AA + rowB * AA + (ec - AA)] = oB;
        }
    }
}

extern "C" void kernel_launch(void* const* d_in, const int* in_sizes, int n_in,
                              void* d_out, int out_size) {
    const float* state = (const float*)d_in[0];
    const float* rW1   = (const float*)d_in[1];
    const float* rb1   = (const float*)d_in[2];
    const float* rW2   = (const float*)d_in[3];
    const float* rb2   = (const float*)d_in[4];
    const float* eW1   = (const float*)d_in[5];
    const float* eb1   = (const float*)d_in[6];
    const float* eg1   = (const float*)d_in[7];
    const float* ebt1  = (const float*)d_in[8];
    const float* eW2   = (const float*)d_in[9];
    const float* eb2   = (const float*)d_in[10];
    const float* eg2   = (const float*)d_in[11];
    const float* ebt2  = (const float*)d_in[12];
    const float* eW3   = (const float*)d_in[13];
    const float* eb3   = (const float*)d_in[14];
    const float* vW1   = (const float*)d_in[15];
    const float* vb1   = (const float*)d_in[16];
    const float* vg    = (const float*)d_in[17];
    const float* vbt   = (const float*)d_in[18];
    const float* vW2   = (const float*)d_in[19];
    const float* vb2   = (const float*)d_in[20];
    const float* vW3   = (const float*)d_in[21];
    const float* vb3   = (const float*)d_in[22];
    float* out = (float*)d_out;

    cudaFuncSetAttribute(moe_fused_kernel,
                         cudaFuncAttributeMaxDynamicSharedMemorySize, SMEM_BYTES);

    moe_fused_kernel<<<2 * NTILES, NT, SMEM_BYTES>>>(
        state, rW1, rb1, rW2, rb2,
        eW1, eb1, eg1, ebt1, eW2, eb2, eg2, ebt2, eW3, eb3,
        vW1, vb1, vg, vbt, vW2, vb2, vW3, vb3, out);
}